// round 1
// baseline (speedup 1.0000x reference)
#include <cuda_runtime.h>

#define SEQ    2048
#define EMBED  128
#define VOCAB  50257
#define TS     64
#define TV     64
#define PAD    68   // padded transposed-row stride (keeps 16B alignment, reduces STS conflicts)

extern __shared__ float smem[];

__global__ void __launch_bounds__(256, 1)
interference_kernel(const float* __restrict__ psi_r,
                    const float* __restrict__ psi_i,
                    const float* __restrict__ pat_r,
                    const float* __restrict__ pat_i,
                    const float* __restrict__ W,
                    const float* __restrict__ bias,
                    float* __restrict__ out)
{
    // Transposed SMEM tiles: [EMBED][PAD], columns 0..63 used.
    float* Ar = smem;
    float* Ai = Ar + EMBED * PAD;
    float* Br = Ai + EMBED * PAD;
    float* Bi = Br + EMBED * PAD;
    float* Bw = Bi + EMBED * PAD;

    const int s0  = blockIdx.x * TS;
    const int v0  = blockIdx.y * TV;
    const int tid = threadIdx.x;

    // ---- Load A tiles (psi_real / psi_imag), transpose into SMEM ----
    // idx -> (c4_lo = idx&3, r = (idx>>2)&63, c4_hi = idx>>8); c4 = c4_hi*4+c4_lo
    // Within a warp: 8 rows x 4 float4 -> coalesced 64B runs; STS is 2-way conflicted (load phase only).
    for (int idx = tid; idx < TS * EMBED / 4; idx += 256) {
        const int c4_lo = idx & 3;
        const int r     = (idx >> 2) & 63;
        const int c4    = ((idx >> 8) << 2) | c4_lo;   // 0..31
        const float4 vr = *(const float4*)(psi_r + (size_t)(s0 + r) * EMBED + c4 * 4);
        const float4 vi = *(const float4*)(psi_i + (size_t)(s0 + r) * EMBED + c4 * 4);
        const int k = c4 * 4;
        Ar[(k + 0) * PAD + r] = vr.x;
        Ar[(k + 1) * PAD + r] = vr.y;
        Ar[(k + 2) * PAD + r] = vr.z;
        Ar[(k + 3) * PAD + r] = vr.w;
        Ai[(k + 0) * PAD + r] = vi.x;
        Ai[(k + 1) * PAD + r] = vi.y;
        Ai[(k + 2) * PAD + r] = vi.z;
        Ai[(k + 3) * PAD + r] = vi.w;
    }

    // ---- Load B tiles (patterns_real / patterns_imag / W), transpose, guard V tail ----
    for (int idx = tid; idx < TV * EMBED / 4; idx += 256) {
        const int c4_lo = idx & 3;
        const int r     = (idx >> 2) & 63;
        const int c4    = ((idx >> 8) << 2) | c4_lo;
        const int v     = v0 + r;
        float4 vr = make_float4(0.f, 0.f, 0.f, 0.f);
        float4 vi = make_float4(0.f, 0.f, 0.f, 0.f);
        float4 vw = make_float4(0.f, 0.f, 0.f, 0.f);
        if (v < VOCAB) {
            vr = *(const float4*)(pat_r + (size_t)v * EMBED + c4 * 4);
            vi = *(const float4*)(pat_i + (size_t)v * EMBED + c4 * 4);
            vw = *(const float4*)(W     + (size_t)v * EMBED + c4 * 4);
        }
        const int k = c4 * 4;
        Br[(k + 0) * PAD + r] = vr.x;
        Br[(k + 1) * PAD + r] = vr.y;
        Br[(k + 2) * PAD + r] = vr.z;
        Br[(k + 3) * PAD + r] = vr.w;
        Bi[(k + 0) * PAD + r] = vi.x;
        Bi[(k + 1) * PAD + r] = vi.y;
        Bi[(k + 2) * PAD + r] = vi.z;
        Bi[(k + 3) * PAD + r] = vi.w;
        Bw[(k + 0) * PAD + r] = vw.x;
        Bw[(k + 1) * PAD + r] = vw.y;
        Bw[(k + 2) * PAD + r] = vw.z;
        Bw[(k + 3) * PAD + r] = vw.w;
    }

    __syncthreads();

    const int tx = tid & 15;
    const int ty = tid >> 4;
    const int sr = ty * 4;   // local S row base
    const int vc = tx * 4;   // local V col base

    float re[4][4] = {{0.f}};
    float im[4][4] = {{0.f}};
    float ln[4][4] = {{0.f}};

    #pragma unroll 4
    for (int k = 0; k < EMBED; k++) {
        const float4 a_r = *(const float4*)(Ar + k * PAD + sr);
        const float4 a_i = *(const float4*)(Ai + k * PAD + sr);
        const float4 b_r = *(const float4*)(Br + k * PAD + vc);
        const float4 b_i = *(const float4*)(Bi + k * PAD + vc);
        const float4 b_w = *(const float4*)(Bw + k * PAD + vc);

        const float arr[4] = {a_r.x, a_r.y, a_r.z, a_r.w};
        const float aii[4] = {a_i.x, a_i.y, a_i.z, a_i.w};
        const float brr[4] = {b_r.x, b_r.y, b_r.z, b_r.w};
        const float bii[4] = {b_i.x, b_i.y, b_i.z, b_i.w};
        const float bww[4] = {b_w.x, b_w.y, b_w.z, b_w.w};

        #pragma unroll
        for (int i = 0; i < 4; i++) {
            #pragma unroll
            for (int j = 0; j < 4; j++) {
                re[i][j] = fmaf(arr[i], brr[j], re[i][j]);
                re[i][j] = fmaf(aii[i], bii[j], re[i][j]);
                im[i][j] = fmaf(arr[i], bii[j], im[i][j]);
                im[i][j] = fmaf(-aii[i], brr[j], im[i][j]);
                ln[i][j] = fmaf(arr[i], bww[j], ln[i][j]);
            }
        }
    }

    // ---- Epilogue: |score|^2 + linear + bias ----
    #pragma unroll
    for (int i = 0; i < 4; i++) {
        const size_t srow = (size_t)(s0 + sr + i) * VOCAB;
        #pragma unroll
        for (int j = 0; j < 4; j++) {
            const int v = v0 + vc + j;
            if (v < VOCAB) {
                out[srow + v] = re[i][j] * re[i][j]
                              + im[i][j] * im[i][j]
                              + ln[i][j] + bias[v];
            }
        }
    }
}

extern "C" void kernel_launch(void* const* d_in, const int* in_sizes, int n_in,
                              void* d_out, int out_size)
{
    const float* psi_r = (const float*)d_in[0];
    const float* psi_i = (const float*)d_in[1];
    const float* pat_r = (const float*)d_in[2];
    const float* pat_i = (const float*)d_in[3];
    const float* W     = (const float*)d_in[4];
    const float* bias  = (const float*)d_in[5];
    float* out = (float*)d_out;

    const size_t smem_bytes = 5ull * EMBED * PAD * sizeof(float);  // 170 KB
    cudaFuncSetAttribute(interference_kernel,
                         cudaFuncAttributeMaxDynamicSharedMemorySize,
                         (int)smem_bytes);

    dim3 grid(SEQ / TS, (VOCAB + TV - 1) / TV);   // (32, 786) — S fastest for B reuse in L2
    interference_kernel<<<grid, 256, smem_bytes>>>(psi_r, psi_i, pat_r, pat_i, W, bias, out);
}

// round 4
// speedup vs baseline: 3.4437x; 3.4437x over previous
#include <cuda_runtime.h>
#include <cstdint>

#define SEQ    2048
#define EMBED  128
#define VOCAB  50257
#define VPAD   50304              // 393 * 128
#define NSBLK  16                 // SEQ / 128
#define NVBLK  393                // VPAD / 128

// A_cat: per s-block, 8 k-chunks of 32 (K=256: [Pr|Pi]) in fragment order
// chunk = 16KB = 4096 floats = [m16(8)][k8(4)] blocks of 128 floats (32 lanes x 4 regs)
#define A_BLK_FLOATS   32768      // 8 chunks * 4096
// B: per v-block: [n8(16)][k8(4)] blocks of 64 floats (32 lanes x 2 regs) per chunk
#define BC_BLK_FLOATS  32768      // 8 chunks (K=256)
#define BW_BLK_FLOATS  16384      // 4 chunks (K=128)

__device__ __align__(16) float g_A  [(size_t)NSBLK * A_BLK_FLOATS];    //   2 MB
__device__ __align__(16) float g_Bre[(size_t)NVBLK * BC_BLK_FLOATS];   //  51.5 MB
__device__ __align__(16) float g_Bim[(size_t)NVBLK * BC_BLK_FLOATS];   //  51.5 MB
__device__ __align__(16) float g_Bw [(size_t)NVBLK * BW_BLK_FLOATS];   //  25.8 MB

// ---------------- helpers ----------------
__device__ __forceinline__ uint32_t smem_u32_of(const void* p) {
    uint32_t a;
    asm("{ .reg .u64 t; cvta.to.shared.u64 t, %1; cvt.u32.u64 %0, t; }" : "=r"(a) : "l"(p));
    return a;
}
__device__ __forceinline__ float f2tf32(float x) {
    uint32_t r;
    asm("cvt.rna.tf32.f32 %0, %1;" : "=r"(r) : "f"(x));
    return __uint_as_float(r);
}
#define CP16(dst, src) \
    asm volatile("cp.async.cg.shared.global [%0], [%1], 16;" :: "r"(dst), "l"(src) : "memory")
#define CP_COMMIT() asm volatile("cp.async.commit_group;" ::: "memory")
#define CP_WAIT1()  asm volatile("cp.async.wait_group 1;" ::: "memory")

__device__ __forceinline__ void mma8(float* d, const uint32_t* a, const uint32_t* b) {
    asm volatile(
        "mma.sync.aligned.m16n8k8.row.col.f32.tf32.tf32.f32 "
        "{%0,%1,%2,%3}, {%4,%5,%6,%7}, {%8,%9}, {%0,%1,%2,%3};"
        : "+f"(d[0]), "+f"(d[1]), "+f"(d[2]), "+f"(d[3])
        : "r"(a[0]), "r"(a[1]), "r"(a[2]), "r"(a[3]), "r"(b[0]), "r"(b[1]));
}

// ---------------- precompute: pack into HMMA fragment order (tf32-rounded) ----------------
// A fragment (m16n8k8.row): lane=4g+t; a0=A[g][t] a1=A[g+8][t] a2=A[g][t+4] a3=A[g+8][t+4]
__global__ void pack_A(const float* __restrict__ pr, const float* __restrict__ pi) {
    int idx = blockIdx.x * 256 + threadIdx.x;
    if (idx >= NSBLK * A_BLK_FLOATS) return;
    int sblk = idx >> 15;
    int rem  = idx & 32767;
    int chunk = rem >> 12;
    int rem2  = rem & 4095;
    int block = rem2 >> 7;       // m16*4 + k8
    int li    = rem2 & 127;      // lane*4 + reg
    int lane = li >> 2, reg = li & 3;
    int m16 = block >> 2, k8 = block & 3;
    int g = lane >> 2, t = lane & 3;
    int row = sblk * 128 + m16 * 16 + g + (reg & 1) * 8;
    int kv  = chunk * 32 + k8 * 8 + t + (reg >> 1) * 4;     // 0..255
    float v = (kv < 128) ? pr[row * 128 + kv] : pi[row * 128 + kv - 128];
    g_A[idx] = f2tf32(v);
}

// B fragment (col): lane=4g+t; b0=B[k=t][n=g] b1=B[k=t+4][n=g]; B[k][n] = Q[v=n][e=k]
__global__ void pack_Bc(const float* __restrict__ qr, const float* __restrict__ qi) {
    int idx = blockIdx.x * 256 + threadIdx.x;
    if (idx >= NVBLK * BC_BLK_FLOATS) return;
    int vblk = idx >> 15;
    int rem  = idx & 32767;
    int chunk = rem >> 12;
    int rem2  = rem & 4095;
    int block = rem2 >> 6;       // n8*4 + k8
    int li    = rem2 & 63;       // lane*2 + reg
    int lane = li >> 1, reg = li & 1;
    int n8 = block >> 2, k8 = block & 3;
    int g = lane >> 2, t = lane & 3;
    int v  = vblk * 128 + n8 * 8 + g;
    int kv = chunk * 32 + k8 * 8 + t + reg * 4;             // 0..255
    float re = 0.f, im = 0.f;
    if (v < VOCAB) {
        int e = kv & 127;
        float r = qr[(size_t)v * 128 + e];
        float i = qi[(size_t)v * 128 + e];
        if (kv < 128) { re = r;  im = i;  }
        else          { re = i;  im = -r; }
    }
    g_Bre[idx] = f2tf32(re);
    g_Bim[idx] = f2tf32(im);
}

__global__ void pack_Bw(const float* __restrict__ w) {
    int idx = blockIdx.x * 256 + threadIdx.x;
    if (idx >= NVBLK * BW_BLK_FLOATS) return;
    int vblk = idx >> 14;
    int rem  = idx & 16383;
    int chunk = rem >> 12;       // 0..3
    int rem2  = rem & 4095;
    int block = rem2 >> 6;
    int li    = rem2 & 63;
    int lane = li >> 1, reg = li & 1;
    int n8 = block >> 2, k8 = block & 3;
    int g = lane >> 2, t = lane & 3;
    int v  = vblk * 128 + n8 * 8 + g;
    int kv = chunk * 32 + k8 * 8 + t + reg * 4;             // 0..127
    float x = (v < VOCAB) ? w[(size_t)v * 128 + kv] : 0.f;
    g_Bw[idx] = f2tf32(x);
}

// ---------------- main kernel ----------------
#define SMEM_A_BYTES 131072
#define SMEM_TOTAL   (SMEM_A_BYTES + 32768)
#define NSTEP 20

__device__ __forceinline__ const float* bsrc(int cb, int vblk) {
    if (cb < 8)  return g_Bre + (size_t)vblk * BC_BLK_FLOATS + (size_t)cb * 4096;
    if (cb < 16) return g_Bim + (size_t)vblk * BC_BLK_FLOATS + (size_t)(cb - 8) * 4096;
    return g_Bw + (size_t)vblk * BW_BLK_FLOATS + (size_t)(cb - 16) * 4096;
}

extern __shared__ char smem[];

__global__ void __launch_bounds__(256, 1)
interference_tf32_kernel(const float* __restrict__ bias, float* __restrict__ out)
{
    const int tid  = threadIdx.x;
    const int sblk = blockIdx.x;
    const int vblk = blockIdx.y;
    const int s0 = sblk * 128;
    const int v0 = vblk * 128;

    const uint32_t smA = smem_u32_of(smem);
    const uint32_t smB = smA + SMEM_A_BYTES;

    // ---- prologue: A resident (8 chunks, 128KB) + B0, B1 ----
    {
        const char* asp = (const char*)(g_A + (size_t)sblk * A_BLK_FLOATS) + tid * 16;
        #pragma unroll
        for (int it = 0; it < 32; it++)
            CP16(smA + tid * 16 + it * 4096, asp + it * 4096);
        const char* b0 = (const char*)bsrc(0, vblk) + tid * 16;
        #pragma unroll
        for (int it = 0; it < 4; it++)
            CP16(smB + tid * 16 + it * 4096, b0 + it * 4096);
        CP_COMMIT();   // G0: A + B0
        const char* b1 = (const char*)bsrc(1, vblk) + tid * 16;
        #pragma unroll
        for (int it = 0; it < 4; it++)
            CP16(smB + 16384 + tid * 16 + it * 4096, b1 + it * 4096);
        CP_COMMIT();   // G1: B1
    }

    const int lane = tid & 31;
    const int wid  = tid >> 5;
    const int wm   = wid >> 2;     // 0..1  (64-row slab)
    const int wn   = wid & 3;      // 0..3  (32-col slab)
    const uint32_t aw = smA + wm * 8192 + lane * 16;
    const uint32_t bw = smB + wn * 4096 + lane * 8;

    float acc[4][4][4];   // running re^2 + im^2
    float wk [4][4][4];   // current chain accumulator
    #pragma unroll
    for (int i = 0; i < 4; i++)
        #pragma unroll
        for (int j = 0; j < 4; j++)
            #pragma unroll
            for (int r = 0; r < 4; r++) { acc[i][j][r] = 0.f; wk[i][j][r] = 0.f; }

    for (int s = 0; s < NSTEP; s++) {
        CP_WAIT1();
        __syncthreads();

        const int ca = (s < 8) ? s : (s < 16 ? s - 8 : s - 16);
        const uint32_t ab = aw + ca * 16384;
        const uint32_t bb = bw + (s & 1) * 16384;

        #pragma unroll
        for (int k8 = 0; k8 < 4; k8++) {
            uint32_t A[4][4], B[4][2];
            #pragma unroll
            for (int i = 0; i < 4; i++)
                asm volatile("ld.shared.v4.b32 {%0,%1,%2,%3}, [%4];"
                    : "=r"(A[i][0]), "=r"(A[i][1]), "=r"(A[i][2]), "=r"(A[i][3])
                    : "r"(ab + i * 2048 + k8 * 512));
            #pragma unroll
            for (int j = 0; j < 4; j++)
                asm volatile("ld.shared.v2.b32 {%0,%1}, [%2];"
                    : "=r"(B[j][0]), "=r"(B[j][1])
                    : "r"(bb + j * 1024 + k8 * 256));
            #pragma unroll
            for (int i = 0; i < 4; i++)
                #pragma unroll
                for (int j = 0; j < 4; j++)
                    mma8(wk[i][j], A[i], B[j]);
        }

        if (s == 7 || s == 15) {   // end of re / im chains: square-add, reset
            #pragma unroll
            for (int i = 0; i < 4; i++)
                #pragma unroll
                for (int j = 0; j < 4; j++)
                    #pragma unroll
                    for (int r = 0; r < 4; r++) {
                        acc[i][j][r] = fmaf(wk[i][j][r], wk[i][j][r], acc[i][j][r]);
                        wk[i][j][r] = 0.f;
                    }
        }

        __syncthreads();
        if (s + 2 < NSTEP) {
            const char* bs = (const char*)bsrc(s + 2, vblk) + tid * 16;
            const uint32_t dst = smB + (s & 1) * 16384 + tid * 16;
            #pragma unroll
            for (int it = 0; it < 4; it++)
                CP16(dst + it * 4096, bs + it * 4096);
        }
        CP_COMMIT();
    }

    // ---- epilogue: fragments -> smem transpose (stride 132) -> coalesced STG ----
    float* ex = (float*)smem;   // 128 * 132 * 4B = 67.6 KB, reuses A region (safe after barrier)
    const int g = lane >> 2, t = lane & 3;

    #pragma unroll
    for (int i = 0; i < 4; i++) {
        #pragma unroll
        for (int j = 0; j < 4; j++) {
            const int m0 = wm * 64 + i * 16 + g;
            const int n0 = wn * 32 + j * 8 + 2 * t;
            ex[m0 * 132 + n0]           = acc[i][j][0] + wk[i][j][0];
            ex[m0 * 132 + n0 + 1]       = acc[i][j][1] + wk[i][j][1];
            ex[(m0 + 8) * 132 + n0]     = acc[i][j][2] + wk[i][j][2];
            ex[(m0 + 8) * 132 + n0 + 1] = acc[i][j][3] + wk[i][j][3];
        }
    }
    __syncthreads();

    float bv[4];
    bool  vok[4];
    #pragma unroll
    for (int cc = 0; cc < 4; cc++) {
        const int v = v0 + lane + cc * 32;
        vok[cc] = (v < VOCAB);
        bv[cc]  = vok[cc] ? bias[v] : 0.f;
    }
    const int rbase = wid * 16;
    #pragma unroll
    for (int rr = 0; rr < 16; rr++) {
        const int lrow = rbase + rr;
        float* orow = out + (size_t)(s0 + lrow) * VOCAB + v0;
        #pragma unroll
        for (int cc = 0; cc < 4; cc++) {
            if (vok[cc])
                orow[lane + cc * 32] = ex[lrow * 132 + lane + cc * 32] + bv[cc];
        }
    }
}

// ---------------- launch ----------------
extern "C" void kernel_launch(void* const* d_in, const int* in_sizes, int n_in,
                              void* d_out, int out_size)
{
    const float* psi_r = (const float*)d_in[0];
    const float* psi_i = (const float*)d_in[1];
    const float* pat_r = (const float*)d_in[2];
    const float* pat_i = (const float*)d_in[3];
    const float* W     = (const float*)d_in[4];
    const float* bias  = (const float*)d_in[5];
    float* out = (float*)d_out;

    pack_A <<<(NSBLK * A_BLK_FLOATS + 255) / 256, 256>>>(psi_r, psi_i);
    pack_Bc<<<(NVBLK * BC_BLK_FLOATS + 255) / 256, 256>>>(pat_r, pat_i);
    pack_Bw<<<(NVBLK * BW_BLK_FLOATS + 255) / 256, 256>>>(W);

    cudaFuncSetAttribute(interference_tf32_kernel,
                         cudaFuncAttributeMaxDynamicSharedMemorySize, SMEM_TOTAL);
    dim3 grid(NSBLK, NVBLK);   // (16, 393); x fastest -> B tiles shared in L2 across s-blocks
    interference_tf32_kernel<<<grid, 256, SMEM_TOTAL>>>(bias, out);
}